// round 4
// baseline (speedup 1.0000x reference)
#include <cuda_runtime.h>
#include <cstdint>
#include <cstddef>

// ---------------------------------------------------------------------------
// Problem constants (from reference): B=8192, N=9 nodes, D=1024, H=4096,
// EDGES=[(2,3,4),(4,5,6),(6,7,8)], NUM_LAYER=3, EPS=0.1, terms=[2,4,6,8].
//
// agg[t=2] = 3*(e4-e3)            + 0.1*e2
// agg[t=4] = 3*(e2+e3+e6-e5)      + 0.1*e4
// agg[t=6] = 3*(e4+e5+e8-e7)      + 0.1*e6
// agg[t=8] = 3*(e6+e7)            + 0.1*e8
// out[t]   = relu(agg @ W1 + b1) @ W2 + b2     -> (4, 8192, 1024) contiguous
// ---------------------------------------------------------------------------

namespace {
constexpr int B_N   = 8192;
constexpr int NODES = 9;
constexpr int D_DIM = 1024;
constexpr int H_DIM = 4096;
constexpr int TERMS = 4;
constexpr int M_TOT = TERMS * B_N;  // 32768
}

// Scratch (allocation-free rule: __device__ globals)
__device__ float g_agg[(size_t)TERMS * B_N * D_DIM];   // 128 MB
__device__ float g_hid[(size_t)TERMS * B_N * H_DIM];   // 512 MB

// ---------------------------------------------------------------------------
// Aggregation kernel: one thread per (b, k-float4); computes all 4 terms,
// reading each embedding slice exactly once.
// ---------------------------------------------------------------------------
__device__ __forceinline__ float4 f4_comb3(float ca, float4 a, float cb, float4 b,
                                           float cc, float4 c) {
    float4 r;
    r.x = ca*a.x + cb*b.x + cc*c.x;
    r.y = ca*a.y + cb*b.y + cc*c.y;
    r.z = ca*a.z + cb*b.z + cc*c.z;
    r.w = ca*a.w + cb*b.w + cc*c.w;
    return r;
}
__device__ __forceinline__ float4 f4_comb5(float ca, float4 a, float cb, float4 b,
                                           float cc, float4 c, float cd, float4 d,
                                           float ce, float4 e) {
    float4 r;
    r.x = ca*a.x + cb*b.x + cc*c.x + cd*d.x + ce*e.x;
    r.y = ca*a.y + cb*b.y + cc*c.y + cd*d.y + ce*e.y;
    r.z = ca*a.z + cb*b.z + cc*c.z + cd*d.z + ce*e.z;
    r.w = ca*a.w + cb*b.w + cc*c.w + cd*d.w + ce*e.w;
    return r;
}

__global__ void agg_kernel(const float* __restrict__ emb) {
    constexpr int KV = D_DIM / 4;  // 256 float4 per row
    size_t idx = (size_t)blockIdx.x * blockDim.x + threadIdx.x;
    if (idx >= (size_t)B_N * KV) return;
    int b  = (int)(idx / KV);
    int kv = (int)(idx % KV);

    const float4* e4p = reinterpret_cast<const float4*>(emb);
    size_t base = ((size_t)b * NODES) * KV + kv;
    float4 n2 = e4p[base + 2*KV];
    float4 n3 = e4p[base + 3*KV];
    float4 n4 = e4p[base + 4*KV];
    float4 n5 = e4p[base + 5*KV];
    float4 n6 = e4p[base + 6*KV];
    float4 n7 = e4p[base + 7*KV];
    float4 n8 = e4p[base + 8*KV];

    float4* A = reinterpret_cast<float4*>(g_agg);
    size_t tstride = (size_t)B_N * KV;
    size_t o = (size_t)b * KV + kv;

    A[o + 0*tstride] = f4_comb3(0.1f, n2, -3.0f, n3, 3.0f, n4);
    A[o + 1*tstride] = f4_comb5(3.0f, n2, 3.0f, n3, 0.1f, n4, -3.0f, n5, 3.0f, n6);
    A[o + 2*tstride] = f4_comb5(3.0f, n4, 3.0f, n5, 0.1f, n6, -3.0f, n7, 3.0f, n8);
    A[o + 3*tstride] = f4_comb3(3.0f, n6, 3.0f, n7, 0.1f, n8);
}

// ---------------------------------------------------------------------------
// TF32 tensor-core GEMM: C[M,N] = op(A[M,K] @ B[K,N] + bias[N]), op = relu?
// CTA tile 128x128x32, 256 threads (8 warps: 2x4), warp tile 64x32,
// mma.sync.m16n8k8 tf32, cp.async double-buffered smem.
// M,K,N all multiples of tile dims here (no bounds checks).
// ---------------------------------------------------------------------------
__device__ __forceinline__ unsigned f2tf(float x) {
    unsigned r;
    asm("cvt.rna.tf32.f32 %0, %1;" : "=r"(r) : "f"(x));
    return r;
}

template <bool RELU>
__global__ void __launch_bounds__(256)
gemm_tf32(const float* __restrict__ A, const float* __restrict__ Bm,
          const float* __restrict__ bias, float* __restrict__ C,
          int M, int N, int K)
{
    constexpr int BM = 128, BN = 128, BK = 32;
    constexpr int AS_STRIDE = BK + 4;    // 36: stride % 32 == 4 -> conflict-free frags
    constexpr int BS_STRIDE = BN + 8;    // 136: stride % 32 == 8 -> conflict-free frags
    constexpr int AS_BUF = BM * AS_STRIDE;  // floats
    constexpr int BS_BUF = BK * BS_STRIDE;

    extern __shared__ float smem[];
    float* As = smem;                 // [2][BM][AS_STRIDE]
    float* Bs = smem + 2 * AS_BUF;    // [2][BK][BS_STRIDE]

    const int tid  = threadIdx.x;
    const int lane = tid & 31;
    const int warp = tid >> 5;
    const int warp_m = warp >> 2;   // 0..1
    const int warp_n = warp & 3;    // 0..3
    const int m_cta = blockIdx.y * BM;
    const int n_cta = blockIdx.x * BN;

    // Loader mapping (coalesced 16B global loads)
    const int a_row  = tid >> 3;    // 0..31
    const int a_kq   = tid & 7;     // k-offset = a_kq*4
    const int b_krow = tid >> 5;    // 0..7
    const int b_nq   = tid & 31;    // n-offset = b_nq*4

    const float* Ag = A + (size_t)m_cta * K;

    auto issue_tile = [&](int kt, int buf) {
        const int k0 = kt * BK;
        #pragma unroll
        for (int p = 0; p < 4; ++p) {
            int row = p * 32 + a_row;
            const float* src = Ag + (size_t)row * K + k0 + a_kq * 4;
            unsigned dst = (unsigned)__cvta_generic_to_shared(
                As + buf * AS_BUF + row * AS_STRIDE + a_kq * 4);
            // A is streaming (each tile read by one CTA row): bypass L1
            asm volatile("cp.async.cg.shared.global [%0], [%1], 16;\n"
                         :: "r"(dst), "l"(src));
        }
        #pragma unroll
        for (int p = 0; p < 4; ++p) {
            int k = p * 8 + b_krow;
            const float* src = Bm + (size_t)(k0 + k) * N + n_cta + b_nq * 4;
            unsigned dst = (unsigned)__cvta_generic_to_shared(
                Bs + buf * BS_BUF + k * BS_STRIDE + b_nq * 4);
            // B is the weight matrix, reused by every CTA in the same column:
            // allow L1 caching
            asm volatile("cp.async.ca.shared.global [%0], [%1], 16;\n"
                         :: "r"(dst), "l"(src));
        }
        asm volatile("cp.async.commit_group;\n");
    };

    float acc[4][4][4];
    #pragma unroll
    for (int mt = 0; mt < 4; ++mt)
        #pragma unroll
        for (int nt = 0; nt < 4; ++nt)
            #pragma unroll
            for (int r = 0; r < 4; ++r) acc[mt][nt][r] = 0.0f;

    const int KT = K / BK;
    issue_tile(0, 0);

    for (int kt = 0; kt < KT; ++kt) {
        const int buf = kt & 1;
        if (kt + 1 < KT) {
            issue_tile(kt + 1, (kt + 1) & 1);
            asm volatile("cp.async.wait_group 1;\n" ::: "memory");
        } else {
            asm volatile("cp.async.wait_group 0;\n" ::: "memory");
        }
        __syncthreads();

        const float* Asb = As + buf * AS_BUF;
        const float* Bsb = Bs + buf * BS_BUF;

        #pragma unroll
        for (int ks = 0; ks < 4; ++ks) {
            const int kk = ks * 8 + (lane & 3);
            unsigned af[4][4];
            #pragma unroll
            for (int mt = 0; mt < 4; ++mt) {
                int m0 = warp_m * 64 + mt * 16 + (lane >> 2);
                af[mt][0] = f2tf(Asb[m0 * AS_STRIDE + kk]);
                af[mt][1] = f2tf(Asb[(m0 + 8) * AS_STRIDE + kk]);
                af[mt][2] = f2tf(Asb[m0 * AS_STRIDE + kk + 4]);
                af[mt][3] = f2tf(Asb[(m0 + 8) * AS_STRIDE + kk + 4]);
            }
            unsigned bf[4][2];
            #pragma unroll
            for (int nt = 0; nt < 4; ++nt) {
                int n0 = warp_n * 32 + nt * 8 + (lane >> 2);
                bf[nt][0] = f2tf(Bsb[kk * BS_STRIDE + n0]);
                bf[nt][1] = f2tf(Bsb[(kk + 4) * BS_STRIDE + n0]);
            }
            #pragma unroll
            for (int mt = 0; mt < 4; ++mt)
                #pragma unroll
                for (int nt = 0; nt < 4; ++nt) {
                    asm volatile(
                        "mma.sync.aligned.m16n8k8.row.col.f32.tf32.tf32.f32 "
                        "{%0,%1,%2,%3}, {%4,%5,%6,%7}, {%8,%9}, {%0,%1,%2,%3};\n"
                        : "+f"(acc[mt][nt][0]), "+f"(acc[mt][nt][1]),
                          "+f"(acc[mt][nt][2]), "+f"(acc[mt][nt][3])
                        : "r"(af[mt][0]), "r"(af[mt][1]),
                          "r"(af[mt][2]), "r"(af[mt][3]),
                          "r"(bf[nt][0]), "r"(bf[nt][1]));
                }
        }
        __syncthreads();
    }

    // Epilogue: bias (+ optional relu), direct global stores (float2 pairs)
    #pragma unroll
    for (int mt = 0; mt < 4; ++mt) {
        const int rbase = m_cta + warp_m * 64 + mt * 16 + (lane >> 2);
        #pragma unroll
        for (int nt = 0; nt < 4; ++nt) {
            const int col = n_cta + warp_n * 32 + nt * 8 + (lane & 3) * 2;
            const float bv0 = bias[col], bv1 = bias[col + 1];
            float v0 = acc[mt][nt][0] + bv0;
            float v1 = acc[mt][nt][1] + bv1;
            float v2 = acc[mt][nt][2] + bv0;
            float v3 = acc[mt][nt][3] + bv1;
            if (RELU) {
                v0 = fmaxf(v0, 0.0f); v1 = fmaxf(v1, 0.0f);
                v2 = fmaxf(v2, 0.0f); v3 = fmaxf(v3, 0.0f);
            }
            *reinterpret_cast<float2*>(C + (size_t)rbase * N + col) =
                make_float2(v0, v1);
            *reinterpret_cast<float2*>(C + (size_t)(rbase + 8) * N + col) =
                make_float2(v2, v3);
        }
    }
}

// ---------------------------------------------------------------------------
// Launch
// ---------------------------------------------------------------------------
extern "C" void kernel_launch(void* const* d_in, const int* in_sizes, int n_in,
                              void* d_out, int out_size)
{
    (void)in_sizes; (void)n_in; (void)out_size;
    const float* emb = (const float*)d_in[0];
    const float* W1  = (const float*)d_in[1];
    const float* b1  = (const float*)d_in[2];
    const float* W2  = (const float*)d_in[3];
    const float* b2  = (const float*)d_in[4];
    float* out = (float*)d_out;

    constexpr int SMEM_BYTES =
        (2 * 128 * 36 + 2 * 32 * 136) * (int)sizeof(float);  // 71680

    cudaFuncSetAttribute(gemm_tf32<true>,
                         cudaFuncAttributeMaxDynamicSharedMemorySize, SMEM_BYTES);
    cudaFuncSetAttribute(gemm_tf32<false>,
                         cudaFuncAttributeMaxDynamicSharedMemorySize, SMEM_BYTES);

    void* pA = nullptr;
    void* pH = nullptr;
    cudaGetSymbolAddress(&pA, g_agg);
    cudaGetSymbolAddress(&pH, g_hid);
    float* agg = (float*)pA;
    float* hid = (float*)pH;

    // 1) Aggregation: (4, 8192, 1024)
    {
        const int total = B_N * (D_DIM / 4);  // 2,097,152 threads
        agg_kernel<<<total / 256, 256>>>(emb);
    }

    // 2) hidden = relu(agg @ W1 + b1): M=32768, K=1024, N=4096
    {
        dim3 grid(H_DIM / 128, M_TOT / 128);  // (32, 256)
        gemm_tf32<true><<<grid, 256, SMEM_BYTES>>>(agg, W1, b1, hid,
                                                   M_TOT, H_DIM, D_DIM);
    }

    // 3) out = hid @ W2 + b2: M=32768, K=4096, N=1024 -> exactly (4,8192,1024)
    {
        dim3 grid(D_DIM / 128, M_TOT / 128);  // (8, 256)
        gemm_tf32<false><<<grid, 256, SMEM_BYTES>>>(hid, W2, b2, out,
                                                    M_TOT, D_DIM, H_DIM);
    }
}